// round 15
// baseline (speedup 1.0000x reference)
#include <cuda_runtime.h>
#include <cstdint>

// Problem constants
#define Bb 512
#define Tt 512
#define Ff 32
#define Hh 128
#define Ll 5
#define ROWS 4          // batch rows per CTA
#define KH2 32          // h k-pairs per kh-half (total h k-pairs = 64)
#define KHT 64          // total h k-pairs (H/2)
#define KWS 28          // smem-resident kk per half for gate g0+256
#define KW1 4           // reg-resident tail kk for gate g0+256 (KH2 - KWS)
#define KX 16           // x k-pairs (total)
#define NTHREADS 512

// ---------------- smem layout ----------------
struct __align__(16) Smem {
    float2 wlo[2][KWS][256];  // 114688 B: gate (g0+256) h-weights: [kh][kk][g0], kk<28
    float2 wx[KX][2][256];    // 65536 B:  x-weights: [k2x][kh][g0] -> gate g0 + kh*256
    float  red[2][ROWS][512]; // 16384 B:  per-kh h-partials
    float  xred[2][ROWS][512];// 16384 B:  double-buffered x-partials (+bias)
    float2 hx[KHT][ROWS];     // 2048 B:   h state: hx[k2][r] = (h[2k2], h[2k2+1])
    float2 xbuf[2][KX][ROWS]; // 1024 B:   double-buffered x_t slices
};
// total 216,064 B (dynamic smem; ~16 KB under the sm_100a opt-in cap)

// packed f32x2 FMA (Blackwell)
__device__ __forceinline__ unsigned long long ffma2(unsigned long long a,
                                                    unsigned long long b,
                                                    unsigned long long c) {
    unsigned long long d;
    asm("fma.rn.f32x2 %0, %1, %2, %3;" : "=l"(d) : "l"(a), "l"(b), "l"(c));
    return d;
}
__device__ __forceinline__ float hsum2(unsigned long long a) {
    float2 v = *reinterpret_cast<float2*>(&a);
    return v.x + v.y;
}
__device__ __forceinline__ float sigf(float v) {
    return __fdividef(1.f, 1.f + __expf(-v));
}
__device__ __forceinline__ float tanh_fast(float v) {
    float a = fabsf(v);
    float e = __expf(-2.f * a);
    float r = __fdividef(1.f - e, 1.f + e);
    return copysignf(r, v);
}

// ---------------- kernel ----------------
// 128 CTAs x 512 threads. CTA b owns batch rows [4b, 4b+4) and all 512 gate rows.
// Thread t: kh = t>>8 (h-k half: k2 in [32kh, 32kh+32)), g0 = t&255 -> gates g0
// (weights in 32 f32x2 REGISTERS) and g0+256 (28 kk from smem + 4 kk in regs).
// The x-contribution (independent of h!) for step t+1 is computed DURING step
// t's tail, split by gate (kh=0 -> gate g0, kh=1 -> gate g0+256), into double-
// buffered xred (bias folded). Per step (2 syncs):
//   GEMM-h: 32 iters x (2 broadcast LDS.128 h + <=1 LDS.64 w + 8 FFMA2)
//   STS red[kh]; loader STS x(t+1)->xbuf; BAR;
//   update (red0+red1+xred[t&1] -> c,h) overlapped with x-GEMM(t+1)->xred; BAR.
__global__ void __launch_bounds__(NTHREADS, 1)
lstm_kernel(const float* __restrict__ x,
            const float* __restrict__ W_ih,
            const float* __restrict__ W_hh,
            const float* __restrict__ b_ih,
            const float* __restrict__ b_hh,
            const float* __restrict__ W_fc,
            const float* __restrict__ b_fc,
            float* __restrict__ out)
{
    extern __shared__ unsigned char smem_raw[];
    Smem* s = reinterpret_cast<Smem*>(smem_raw);
    const int tid  = threadIdx.x;
    const int kh   = tid >> 8;          // h-k half: k2 in [32kh, 32kh+32)
    const int g0   = tid & 255;         // base gate row
    const int gx   = g0 + kh * 256;     // my x-part gate
    const int row0 = blockIdx.x * ROWS;

    // ---- prologue: weights ----
    const float2* whh2 = reinterpret_cast<const float2*>(W_hh);   // row g: 64 float2
    const float2* wih2 = reinterpret_cast<const float2*>(W_ih);   // row g: 16 float2
    unsigned long long Wr[KH2];                                   // gate g0, my k-half
    unsigned long long Wr1c[KW1];                                 // gate g0+256, tail kk
    #pragma unroll
    for (int kk = 0; kk < KH2; ++kk) {
        int k2 = kh * KH2 + kk;
        float2 v0 = __ldg(whh2 + (size_t)g0 * 64 + k2);
        Wr[kk] = *reinterpret_cast<unsigned long long*>(&v0);
        float2 v1 = __ldg(whh2 + (size_t)(g0 + 256) * 64 + k2);
        if (kk < KWS) s->wlo[kh][kk][g0] = v1;
        else          Wr1c[kk - KWS] = *reinterpret_cast<unsigned long long*>(&v1);
    }
    #pragma unroll
    for (int k2x = 0; k2x < KX; ++k2x)
        s->wx[k2x][kh][g0] = __ldg(wih2 + (size_t)gx * 16 + k2x);
    const float cbx = b_ih[gx] + b_hh[gx];

    // ---- init: zero ALL 64 h k-pairs, x(t=0) -> xbuf[0] ----
    if (tid < 256) s->hx[tid >> 2][tid & 3] = make_float2(0.f, 0.f);
    const int xr = (tid >> 5) & 3, xf = tid & 31;          // x-loader role (tid<128)
    const float* xptr = x + (size_t)(row0 + xr) * Tt * Ff + xf;
    if (tid < 128)
        reinterpret_cast<float*>(&s->xbuf[0][xf >> 1][xr])[xf & 1] = __ldg(xptr);
    __syncthreads();

    // ---- x-GEMM for t=0 -> xred[0] ----
    {
        unsigned long long ax[4] = {0ull, 0ull, 0ull, 0ull};
        #pragma unroll
        for (int k2x = 0; k2x < KX; ++k2x) {
            ulonglong2 xAB = *reinterpret_cast<const ulonglong2*>(&s->xbuf[0][k2x][0]);
            ulonglong2 xCD = *reinterpret_cast<const ulonglong2*>(&s->xbuf[0][k2x][2]);
            unsigned long long w = *reinterpret_cast<const unsigned long long*>(&s->wx[k2x][kh][g0]);
            ax[0] = ffma2(xAB.x, w, ax[0]); ax[1] = ffma2(xAB.y, w, ax[1]);
            ax[2] = ffma2(xCD.x, w, ax[2]); ax[3] = ffma2(xCD.y, w, ax[3]);
        }
        #pragma unroll
        for (int r = 0; r < ROWS; ++r) s->xred[0][r][gx] = hsum2(ax[r]) + cbx;
    }
    __syncthreads();

    // ---- steady-state roles ----
    const int ur = tid >> 7;            // update: batch row
    const int uj = tid & 127;           // update: h column
    float c_ = 0.f;

    const unsigned long long* hq =
        reinterpret_cast<const unsigned long long*>(s->hx) + (size_t)kh * KH2 * ROWS;
    const unsigned long long* w1p =
        reinterpret_cast<const unsigned long long*>(s->wlo) + (size_t)kh * KWS * 256 + g0;

    for (int st = 0; st < Tt; ++st) {
        // prefetch next x slice (clamped; last-step value is never consumed)
        float xnext = 0.f;
        {
            int tn = st + 1 < Tt ? st + 1 : Tt - 1;
            if (tid < 128) xnext = __ldg(xptr + (size_t)tn * Ff);
        }

        // ---- GEMM-h: 2 gates x 4 rows over my 32 h-k2 ----
        unsigned long long a0[4], a1[4];
        #pragma unroll
        for (int r = 0; r < 4; ++r) { a0[r] = 0ull; a1[r] = 0ull; }
        #pragma unroll
        for (int kk = 0; kk < KH2; ++kk) {
            ulonglong2 hAB = *reinterpret_cast<const ulonglong2*>(hq + kk * 4);     // rows 0,1
            ulonglong2 hCD = *reinterpret_cast<const ulonglong2*>(hq + kk * 4 + 2); // rows 2,3
            unsigned long long w0 = Wr[kk];
            unsigned long long w1 = (kk < KWS) ? w1p[(size_t)kk * 256]
                                               : Wr1c[kk - KWS];
            a0[0] = ffma2(hAB.x, w0, a0[0]); a0[1] = ffma2(hAB.y, w0, a0[1]);
            a0[2] = ffma2(hCD.x, w0, a0[2]); a0[3] = ffma2(hCD.y, w0, a0[3]);
            a1[0] = ffma2(hAB.x, w1, a1[0]); a1[1] = ffma2(hAB.y, w1, a1[1]);
            a1[2] = ffma2(hCD.x, w1, a1[2]); a1[3] = ffma2(hCD.y, w1, a1[3]);
        }
        #pragma unroll
        for (int r = 0; r < ROWS; ++r) {
            s->red[kh][r][g0]       = hsum2(a0[r]);
            s->red[kh][r][g0 + 256] = hsum2(a1[r]);
        }
        if (tid < 128)
            reinterpret_cast<float*>(&s->xbuf[(st + 1) & 1][xf >> 1][xr])[xf & 1] = xnext;
        __syncthreads();

        // ---- update (row ur, col uj): red0 + red1 + xred[st&1] ----
        {
            const float* r0 = &s->red[0][ur][0];
            const float* r1 = &s->red[1][ur][0];
            const float* rx = &s->xred[st & 1][ur][0];
            float iv = r0[uj]       + r1[uj]       + rx[uj];
            float fv = r0[uj + 128] + r1[uj + 128] + rx[uj + 128];
            float gv = r0[uj + 256] + r1[uj + 256] + rx[uj + 256];
            float ov = r0[uj + 384] + r1[uj + 384] + rx[uj + 384];
            float c = sigf(fv) * c_ + sigf(iv) * tanh_fast(gv);
            c_ = c;
            float h = sigf(ov) * tanh_fast(c);
            reinterpret_cast<float*>(&s->hx[uj >> 1][ur])[uj & 1] = h;
        }

        // ---- x-GEMM for t+1 -> xred[(st+1)&1] (overlaps update latency) ----
        {
            const int pn = (st + 1) & 1;
            unsigned long long ax[4] = {0ull, 0ull, 0ull, 0ull};
            #pragma unroll
            for (int k2x = 0; k2x < KX; ++k2x) {
                ulonglong2 xAB = *reinterpret_cast<const ulonglong2*>(&s->xbuf[pn][k2x][0]);
                ulonglong2 xCD = *reinterpret_cast<const ulonglong2*>(&s->xbuf[pn][k2x][2]);
                unsigned long long w = *reinterpret_cast<const unsigned long long*>(&s->wx[k2x][kh][g0]);
                ax[0] = ffma2(xAB.x, w, ax[0]); ax[1] = ffma2(xAB.y, w, ax[1]);
                ax[2] = ffma2(xCD.x, w, ax[2]); ax[3] = ffma2(xCD.y, w, ax[3]);
            }
            #pragma unroll
            for (int r = 0; r < ROWS; ++r) s->xred[pn][r][gx] = hsum2(ax[r]) + cbx;
        }
        __syncthreads();
    }

    // ---- FC head on final h ----
    if (tid < ROWS * Ll) {
        int r = tid / Ll, l = tid - r * Ll;
        float acc = b_fc[l];
        const float* wl = W_fc + l * Hh;
        #pragma unroll 16
        for (int k = 0; k < Hh; ++k)
            acc += reinterpret_cast<const float*>(&s->hx[k >> 1][r])[k & 1] * wl[k];
        out[(row0 + r) * Ll + l] = acc;
    }
}

// ---------------- host launch ----------------
extern "C" void kernel_launch(void* const* d_in, const int* in_sizes, int n_in,
                              void* d_out, int out_size) {
    const float* x    = (const float*)d_in[0];
    const float* W_ih = (const float*)d_in[1];
    const float* W_hh = (const float*)d_in[2];
    const float* b_ih = (const float*)d_in[3];
    const float* b_hh = (const float*)d_in[4];
    const float* W_fc = (const float*)d_in[5];
    const float* b_fc = (const float*)d_in[6];
    float* out = (float*)d_out;

    const size_t smem = sizeof(Smem);
    cudaFuncSetAttribute(lstm_kernel, cudaFuncAttributeMaxDynamicSharedMemorySize, (int)smem);
    lstm_kernel<<<Bb / ROWS, NTHREADS, smem>>>(x, W_ih, W_hh, b_ih, b_hh, W_fc, b_fc, out);
}

// round 16
// speedup vs baseline: 1.2122x; 1.2122x over previous
#include <cuda_runtime.h>
#include <cstdint>

// Problem constants
#define Bb 512
#define Tt 512
#define Ff 32
#define Hh 128
#define Ll 5
#define G4 512          // total gate rows (4H)
#define ROWS 4          // batch rows per CTA
#define K2T 80          // (H+F)/2 total packed k-pairs (k2 0..63 = W_hh, 64..79 = W_ih)
#define K2Q 20          // k-pairs per k-quarter
#define KREG 17         // reg-resident k-pairs per register gate
#define KSM  3          // smem tail k-pairs per register gate (K2Q - KREG)
#define NTHREADS 512

// ---------------- smem layout ----------------
struct __align__(16) Smem {
    float2 wlo[4][K2Q][2][128];  // 163840 B: smem gates (g0+256, g0+384): [kq][kk][j][g0]
    float2 whi[4][KSM][2][128];  // 24576 B: reg-gates' tail k2 (g0, g0+128): [kq][kk-KREG][j][g0]
    float2 hx[K2T][ROWS];        // 2560 B: hx[k2][r]; k<128 -> h, k>=128 -> x_t
    float  red[4][ROWS][G4];     // 32768 B: partials, slab d=(r-kq)&3; slab 0 unused
};
// total 223,744 B (dynamic smem; comfortably under cap — 232,448 B failed to launch, R13/R14 lesson)

// packed f32x2 FMA (Blackwell)
__device__ __forceinline__ unsigned long long ffma2(unsigned long long a,
                                                    unsigned long long b,
                                                    unsigned long long c) {
    unsigned long long d;
    asm("fma.rn.f32x2 %0, %1, %2, %3;" : "=l"(d) : "l"(a), "l"(b), "l"(c));
    return d;
}
__device__ __forceinline__ float hsum2(unsigned long long a) {
    float2 v = *reinterpret_cast<float2*>(&a);
    return v.x + v.y;
}
// HW tanh (sm_75+ MUFU.TANH): ~2e-4 abs err, single op
__device__ __forceinline__ float tanh_hw(float v) {
    float r;
    asm("tanh.approx.f32 %0, %1;" : "=f"(r) : "f"(v));
    return r;
}
__device__ __forceinline__ float sig_hw(float v) {
    return fmaf(tanh_hw(0.5f * v), 0.5f, 0.5f);
}
// select one of 4 statically-unrolled values by runtime index (2 SELs, no local mem)
__device__ __forceinline__ float pick4(float v0, float v1, float v2, float v3, int k) {
    float a = (k & 1) ? v1 : v0;
    float b = (k & 1) ? v3 : v2;
    return (k & 2) ? b : a;
}

// ---------------- kernel ----------------
// 128 CTAs x 512 threads. CTA b owns batch rows [4b, 4b+4) and all 512 gate rows.
// Thread t: k-quarter kq = t>>7 (20 k2), gates {g0, g0+128, g0+256, g0+384},
// g0 = t&127. Gates g0, g0+128: 17 of 20 k2 in REGISTERS, 3 from smem; gates
// g0+256, g0+384: all from smem (conflict-free LDS.64). Per step (2 syncs):
//   GEMM 20 iters x (2 broadcast LDS.128 h + 2-4 LDS.64 w + 16 FFMA2);
//   write partials for rows r != kq into slab (r-kq)&3 (12 STS) — the own-row
//   (r == kq) partials stay in REGISTERS; sync;
//   update (row kq, col g0) = own + slabs 1..3 + bias, activations via HW
//   tanh.approx, c in a register, h -> hx; sync.
__global__ void __launch_bounds__(NTHREADS, 1)
lstm_kernel(const float* __restrict__ x,
            const float* __restrict__ W_ih,
            const float* __restrict__ W_hh,
            const float* __restrict__ b_ih,
            const float* __restrict__ b_hh,
            const float* __restrict__ W_fc,
            const float* __restrict__ b_fc,
            float* __restrict__ out)
{
    extern __shared__ unsigned char smem_raw[];
    Smem* s = reinterpret_cast<Smem*>(smem_raw);
    const int tid  = threadIdx.x;
    const int kq   = tid >> 7;          // k-quarter AND my update row
    const int g0   = tid & 127;         // base gate row AND my update column
    const int row0 = blockIdx.x * ROWS;

    // ---- prologue: weights -> regs (g0,g0+128 first 17 k2) and smem ----
    const float2* whh2 = reinterpret_cast<const float2*>(W_hh);   // row g: 64 float2
    const float2* wih2 = reinterpret_cast<const float2*>(W_ih);   // row g: 16 float2
    unsigned long long Wr0[KREG], Wr1[KREG];
    {
        const int base = kq * K2Q;
        #pragma unroll
        for (int kk = 0; kk < K2Q; ++kk) {
            int k2 = base + kk;
            float2 v0 = (k2 < 64) ? __ldg(whh2 + (size_t)g0 * 64 + k2)
                                  : __ldg(wih2 + (size_t)g0 * 16 + (k2 - 64));
            float2 v1 = (k2 < 64) ? __ldg(whh2 + (size_t)(g0 + 128) * 64 + k2)
                                  : __ldg(wih2 + (size_t)(g0 + 128) * 16 + (k2 - 64));
            if (kk < KREG) {
                Wr0[kk] = *reinterpret_cast<unsigned long long*>(&v0);
                Wr1[kk] = *reinterpret_cast<unsigned long long*>(&v1);
            } else {
                s->whi[kq][kk - KREG][0][g0] = v0;
                s->whi[kq][kk - KREG][1][g0] = v1;
            }
            float2 v2 = (k2 < 64) ? __ldg(whh2 + (size_t)(g0 + 256) * 64 + k2)
                                  : __ldg(wih2 + (size_t)(g0 + 256) * 16 + (k2 - 64));
            s->wlo[kq][kk][0][g0] = v2;
            float2 v3 = (k2 < 64) ? __ldg(whh2 + (size_t)(g0 + 384) * 64 + k2)
                                  : __ldg(wih2 + (size_t)(g0 + 384) * 16 + (k2 - 64));
            s->wlo[kq][kk][1][g0] = v3;
        }
    }
    // bias for my 4 gates (added to the register-resident own partial)
    float cb[4];
    #pragma unroll
    for (int j = 0; j < 4; ++j)
        cb[j] = b_ih[g0 + 128 * j] + b_hh[g0 + 128 * j];

    // ---- init state: zero h region (k2 0..63), x(t=0) into k2 64..79 ----
    if (tid < 256) s->hx[tid >> 2][tid & 3] = make_float2(0.f, 0.f);
    const int xr = (tid >> 5) & 3, xf = tid & 31;          // x-loader role for tid<128
    const float* xptr = x + (size_t)(row0 + xr) * Tt * Ff + xf;
    if (tid < 128) {
        float v = __ldg(xptr);
        reinterpret_cast<float*>(&s->hx[64 + (xf >> 1)][xr])[xf & 1] = v;
    }
    __syncthreads();

    float c_ = 0.f;                     // cell state: row kq, col g0

    const unsigned long long* hq =
        reinterpret_cast<const unsigned long long*>(&s->hx[kq * K2Q][0]);
    const unsigned long long* wlo_p =
        reinterpret_cast<const unsigned long long*>(&s->wlo[kq][0][0][g0]);
    const unsigned long long* whi_p =
        reinterpret_cast<const unsigned long long*>(&s->whi[kq][0][0][g0]);
    const int QS = ROWS * G4;           // red slab stride (floats)
    float* redb = &s->red[0][0][g0];    // slab/row addressing done per write
    const float* redr = &s->red[0][kq][g0];  // reader base (slabs 1..3)

    for (int st = 0; st < Tt; ++st) {
        // prefetch next x slice (tid<128)
        float xnext = 0.f;
        if (tid < 128 && st + 1 < Tt) xnext = __ldg(xptr + (size_t)(st + 1) * Ff);

        // ---- GEMM: 4 gates x 4 batch rows, my k-quarter ----
        unsigned long long a0[ROWS], a1[ROWS], a2[ROWS], a3[ROWS];
        #pragma unroll
        for (int r = 0; r < ROWS; ++r) { a0[r] = 0ull; a1[r] = 0ull; a2[r] = 0ull; a3[r] = 0ull; }
        #pragma unroll
        for (int kk = 0; kk < K2Q; ++kk) {
            ulonglong2 hAB = *reinterpret_cast<const ulonglong2*>(hq + kk * 4);     // rows 0,1
            ulonglong2 hCD = *reinterpret_cast<const ulonglong2*>(hq + kk * 4 + 2); // rows 2,3
            unsigned long long w0 = (kk < KREG) ? Wr0[kk]
                                                : whi_p[(size_t)(kk - KREG) * 256];
            unsigned long long w1 = (kk < KREG) ? Wr1[kk]
                                                : whi_p[(size_t)(kk - KREG) * 256 + 128];
            unsigned long long w2 = wlo_p[(size_t)kk * 256];        // wlo[kq][kk][0][g0]
            unsigned long long w3 = wlo_p[(size_t)kk * 256 + 128];  // wlo[kq][kk][1][g0]
            a0[0] = ffma2(hAB.x, w0, a0[0]); a0[1] = ffma2(hAB.y, w0, a0[1]);
            a0[2] = ffma2(hCD.x, w0, a0[2]); a0[3] = ffma2(hCD.y, w0, a0[3]);
            a1[0] = ffma2(hAB.x, w1, a1[0]); a1[1] = ffma2(hAB.y, w1, a1[1]);
            a1[2] = ffma2(hCD.x, w1, a1[2]); a1[3] = ffma2(hCD.y, w1, a1[3]);
            a2[0] = ffma2(hAB.x, w2, a2[0]); a2[1] = ffma2(hAB.y, w2, a2[1]);
            a2[2] = ffma2(hCD.x, w2, a2[2]); a2[3] = ffma2(hCD.y, w2, a2[3]);
            a3[0] = ffma2(hAB.x, w3, a3[0]); a3[1] = ffma2(hAB.y, w3, a3[1]);
            a3[2] = ffma2(hCD.x, w3, a3[2]); a3[3] = ffma2(hCD.y, w3, a3[3]);
        }

        // horizontal sums (all needed either for STS or for the own-row regs)
        float s0[ROWS], s1[ROWS], s2[ROWS], s3[ROWS];
        #pragma unroll
        for (int r = 0; r < ROWS; ++r) {
            s0[r] = hsum2(a0[r]); s1[r] = hsum2(a1[r]);
            s2[r] = hsum2(a2[r]); s3[r] = hsum2(a3[r]);
        }
        // own-row partials stay in registers (row kq)
        float own0 = pick4(s0[0], s0[1], s0[2], s0[3], kq);
        float own1 = pick4(s1[0], s1[1], s1[2], s1[3], kq);
        float own2 = pick4(s2[0], s2[1], s2[2], s2[3], kq);
        float own3 = pick4(s3[0], s3[1], s3[2], s3[3], kq);
        // foreign rows -> slab (r-kq)&3 (12 STS; r==kq skipped, warp-uniform kq)
        #pragma unroll
        for (int r = 0; r < ROWS; ++r) {
            int d = (r - kq) & 3;
            if (d != 0) {
                float* pr = redb + (size_t)d * QS + r * G4;
                pr[0]   = s0[r];
                pr[128] = s1[r];
                pr[256] = s2[r];
                pr[384] = s3[r];
            }
        }
        if (tid < 128 && st + 1 < Tt)
            reinterpret_cast<float*>(&s->hx[64 + (xf >> 1)][xr])[xf & 1] = xnext;
        __syncthreads();

        // ---- update (row kq, col g0): own regs + slabs 1..3 + bias ----
        {
            float iv = own0 + cb[0] + redr[1*QS]       + redr[2*QS]       + redr[3*QS];
            float fv = own1 + cb[1] + redr[1*QS + 128] + redr[2*QS + 128] + redr[3*QS + 128];
            float gv = own2 + cb[2] + redr[1*QS + 256] + redr[2*QS + 256] + redr[3*QS + 256];
            float ov = own3 + cb[3] + redr[1*QS + 384] + redr[2*QS + 384] + redr[3*QS + 384];
            float c = sig_hw(fv) * c_ + sig_hw(iv) * tanh_hw(gv);
            c_ = c;
            float h = sig_hw(ov) * tanh_hw(c);
            reinterpret_cast<float*>(&s->hx[g0 >> 1][kq])[g0 & 1] = h;
        }
        __syncthreads();
    }

    // ---- FC head on final h ----
    if (tid < ROWS * Ll) {
        int r = tid / Ll, l = tid - r * Ll;
        float acc = b_fc[l];
        const float* wl = W_fc + l * Hh;
        #pragma unroll 16
        for (int k = 0; k < Hh; ++k)
            acc += reinterpret_cast<const float*>(&s->hx[k >> 1][r])[k & 1] * wl[k];
        out[(row0 + r) * Ll + l] = acc;
    }
}

// ---------------- host launch ----------------
extern "C" void kernel_launch(void* const* d_in, const int* in_sizes, int n_in,
                              void* d_out, int out_size) {
    const float* x    = (const float*)d_in[0];
    const float* W_ih = (const float*)d_in[1];
    const float* W_hh = (const float*)d_in[2];
    const float* b_ih = (const float*)d_in[3];
    const float* b_hh = (const float*)d_in[4];
    const float* W_fc = (const float*)d_in[5];
    const float* b_fc = (const float*)d_in[6];
    float* out = (float*)d_out;

    const size_t smem = sizeof(Smem);
    cudaFuncSetAttribute(lstm_kernel, cudaFuncAttributeMaxDynamicSharedMemorySize, (int)smem);
    lstm_kernel<<<Bb / ROWS, NTHREADS, smem>>>(x, W_ih, W_hh, b_ih, b_hh, W_fc, b_fc, out);
}